// round 6
// baseline (speedup 1.0000x reference)
#include <cuda_runtime.h>
#include <math.h>

#define NN    4096
#define DD    64
#define FULL  0xFFFFFFFFu

__device__ float        g_scores[256 * NN];
__device__ double       g_acc;
__device__ unsigned int g_done;

__device__ __forceinline__ float dot4(float4 a, float4 b) {
    return a.x * b.x + a.y * b.y + a.z * b.z + a.w * b.w;
}

// ---------------------------------------------------------------------------
// Kernel A: streaming GEMV. 16 lanes per score, 4 consecutive scores per
// thread (4 independent LDG.128 in flight). Warp covers 8 scores -> 512B
// coalesced chunks per load step.
// ---------------------------------------------------------------------------
__global__ __launch_bounds__(256) void scores_kernel(const float* __restrict__ X,
                                                     const float* __restrict__ W,
                                                     const float* __restrict__ bias,
                                                     float* __restrict__ scores,
                                                     int total_scores) {
    const int gid   = blockIdx.x * 256 + threadIdx.x;
    const int group = gid >> 4;          // 4-score group id
    const int l     = gid & 15;          // lane within 16-lane dot group
    const int s0    = group * 4;
    if (s0 >= total_scores) return;

    const float4  wv = reinterpret_cast<const float4*>(W)[l];
    const float4* Xv = reinterpret_cast<const float4*>(X);
    const size_t  base = (size_t)s0 * 16 + l;   // float4 index of (score s0, chunk l)

    const float4 xa = Xv[base];
    const float4 xb = Xv[base + 16];
    const float4 xc = Xv[base + 32];
    const float4 xd = Xv[base + 48];

    float pa = dot4(xa, wv);
    float pb = dot4(xb, wv);
    float pc = dot4(xc, wv);
    float pd = dot4(xd, wv);

    #pragma unroll
    for (int o = 8; o; o >>= 1) {
        pa += __shfl_xor_sync(FULL, pa, o);
        pb += __shfl_xor_sync(FULL, pb, o);
        pc += __shfl_xor_sync(FULL, pc, o);
        pd += __shfl_xor_sync(FULL, pd, o);
    }

    if (l == 0) {
        const float b0 = bias[0];
        float4 out4 = make_float4(pa + b0, pb + b0, pc + b0, pd + b0);
        reinterpret_cast<float4*>(scores)[group] = out4;
    }
}

// ---------------------------------------------------------------------------
// Kernel B: per-row gather + suffix logsumexp scan + NLL accumulation.
// One block (1024 threads) per batch row; 4 elements per thread.
// ---------------------------------------------------------------------------
__global__ __launch_bounds__(1024) void nll_kernel(const float* __restrict__ scores,
                                                   const int* __restrict__ rankings,
                                                   float* __restrict__ out) {
    __shared__ float s_sc[NN];
    __shared__ float s_ws[32];
    __shared__ float s_red[32];
    __shared__ float s_M;

    const int b    = blockIdx.x;
    const int tid  = threadIdx.x;
    const int lane = tid & 31;
    const int wrp  = tid >> 5;

    // Stage scores row (L2-hot) and load rankings.
    const int4 r = reinterpret_cast<const int4*>(rankings + (size_t)b * NN)[tid];
    reinterpret_cast<float4*>(s_sc)[tid] =
        reinterpret_cast<const float4*>(scores + (size_t)b * NN)[tid];
    __syncthreads();

    const float x0 = s_sc[r.x & (NN - 1)];
    const float x1 = s_sc[r.y & (NN - 1)];
    const float x2 = s_sc[r.z & (NN - 1)];
    const float x3 = s_sc[r.w & (NN - 1)];

    // Block max.
    float mx = fmaxf(fmaxf(x0, x1), fmaxf(x2, x3));
    #pragma unroll
    for (int o = 16; o; o >>= 1) mx = fmaxf(mx, __shfl_xor_sync(FULL, mx, o));
    if (lane == 0) s_ws[wrp] = mx;
    __syncthreads();
    if (wrp == 0) {
        float am = s_ws[lane];
        #pragma unroll
        for (int o = 16; o; o >>= 1) am = fmaxf(am, __shfl_xor_sync(FULL, am, o));
        if (lane == 0) s_M = am;
    }
    __syncthreads();
    const float M = s_M;

    // exp-shifted values; additive suffix-sum scan.
    const float e0 = __expf(x0 - M);
    const float e1 = __expf(x1 - M);
    const float e2 = __expf(x2 - M);
    const float e3 = __expf(x3 - M);

    float inc = e0 + e1 + e2 + e3;
    #pragma unroll
    for (int d = 1; d < 32; d <<= 1) {
        const float t = __shfl_down_sync(FULL, inc, d);
        if (lane + d < 32) inc += t;
    }
    if (lane == 0) s_ws[wrp] = inc;
    __syncthreads();
    if (wrp == 0) {
        float av = s_ws[lane];
        #pragma unroll
        for (int d = 1; d < 32; d <<= 1) {
            const float t = __shfl_down_sync(FULL, av, d);
            if (lane + d < 32) av += t;
        }
        s_ws[lane] = av;
    }
    __syncthreads();

    float ex = __shfl_down_sync(FULL, inc, 1);
    ex = (lane < 31) ? ex : 0.0f;
    const float Sc = ex + ((wrp < 31) ? s_ws[wrp + 1] : 0.0f);

    // Replay descending; denom = M + log(S).
    float rs  = Sc;
    float acc = 0.0f;
    rs += e3; acc += (x3 - M) - __logf(rs);
    rs += e2; acc += (x2 - M) - __logf(rs);
    rs += e1; acc += (x1 - M) - __logf(rs);
    rs += e0; acc += (x0 - M) - __logf(rs);

    // Block reduce + completion-counter finalize.
    #pragma unroll
    for (int o = 16; o; o >>= 1) acc += __shfl_xor_sync(FULL, acc, o);
    if (lane == 0) s_red[wrp] = acc;
    __syncthreads();
    if (tid == 0) {
        float t = 0.0f;
        #pragma unroll
        for (int w = 0; w < 32; w++) t += s_red[w];
        atomicAdd(&g_acc, (double)t);
        __threadfence();
        const unsigned int ticket = atomicAdd(&g_done, 1u);
        if (ticket == gridDim.x - 1) {
            out[0] = (float)(-g_acc / (double)gridDim.x);
            g_acc  = 0.0;
            g_done = 0u;
            __threadfence();
        }
    }
}

extern "C" void kernel_launch(void* const* d_in, const int* in_sizes, int n_in,
                              void* d_out, int out_size) {
    const float* X        = (const float*)d_in[0];
    const float* W        = (const float*)d_in[1];
    const float* bias     = (const float*)d_in[2];
    const int*   rankings = (const int*)d_in[3];
    float* out = (float*)d_out;

    const int BN = in_sizes[3];   // B * N scores
    const int B  = BN / NN;

    const int blocksA = (BN + 63) / 64;   // 64 scores per 256-thread block
    scores_kernel<<<blocksA, 256>>>(X, W, bias, g_scores, BN);
    nll_kernel<<<B, 1024>>>(g_scores, rankings, out);
}

// round 7
// speedup vs baseline: 1.4140x; 1.4140x over previous
#include <cuda_runtime.h>
#include <math.h>

#define NN    4096
#define DD    64
#define T     512
#define FULL  0xFFFFFFFFu

__device__ double       g_acc;
__device__ unsigned int g_done;

__device__ __forceinline__ float dot4(float4 a, float4 b) {
    return a.x * b.x + a.y * b.y + a.z * b.z + a.w * b.w;
}

// exp(x) for x in [-90, 0]: FMA-pipe polynomial, no MUFU.
__device__ __forceinline__ float fast_exp(float x) {
    float t  = x * 1.44269504f;          // x * log2(e)
    float kf = floorf(t);
    float f  = t - kf;                    // [0,1)
    float p  = 1.33988744e-3f;
    p = fmaf(p, f, 9.61843736e-3f);
    p = fmaf(p, f, 5.55033247e-2f);
    p = fmaf(p, f, 2.40226479e-1f);
    p = fmaf(p, f, 6.93147203e-1f);
    p = fmaf(p, f, 1.0f);
    int ki = (int)kf;                     // >= -81 here, safe
    return p * __int_as_float((ki + 127) << 23);
}

__global__ __launch_bounds__(T, 2) void fused_kernel(const float* __restrict__ X,
                                                     const float* __restrict__ W,
                                                     const float* __restrict__ bias,
                                                     const int* __restrict__ rankings,
                                                     float* __restrict__ out) {
    __shared__ float s_sc[NN];
    __shared__ float s_ws[16];
    __shared__ float s_red[16];
    __shared__ float s_M;

    const int b    = blockIdx.x;
    const int tid  = threadIdx.x;
    const int lane = tid & 31;
    const int wrp  = tid >> 5;            // 0..15
    const int l4   = lane & 3;            // sub-lane within 4-lane dot group
    const int g8   = lane >> 2;           // group 0..7

    // -------- Phase 1: scores = X[b] @ W + b0 (4 lanes per score) ----------
    const float4* Wv = reinterpret_cast<const float4*>(W);
    const float4 w0 = Wv[l4 * 4 + 0];
    const float4 w1 = Wv[l4 * 4 + 1];
    const float4 w2 = Wv[l4 * 4 + 2];
    const float4 w3 = Wv[l4 * 4 + 3];
    const float  b0 = bias[0];
    const float4* Xv = reinterpret_cast<const float4*>(X + (size_t)b * NN * DD);

    #pragma unroll 2
    for (int i = 0; i < NN / 128; i++) {              // 32 iters, 128 scores each
        const int s = i * 128 + wrp * 8 + g8;
        const float4* xp = Xv + (size_t)s * 16 + l4 * 4;
        const float4 xa = xp[0];
        const float4 xb = xp[1];
        const float4 xc = xp[2];
        const float4 xd = xp[3];
        float p = dot4(xa, w0) + dot4(xb, w1) + dot4(xc, w2) + dot4(xd, w3);
        p += __shfl_xor_sync(FULL, p, 2);
        p += __shfl_xor_sync(FULL, p, 1);
        if (l4 == 0) s_sc[s] = p + b0;
    }
    __syncthreads();

    // -------- Phase 2: gather 8 elements (positions 8*tid .. 8*tid+7) -------
    const int4 r0 = reinterpret_cast<const int4*>(rankings + (size_t)b * NN)[2 * tid];
    const int4 r1 = reinterpret_cast<const int4*>(rankings + (size_t)b * NN)[2 * tid + 1];
    float xv[8];
    xv[0] = s_sc[r0.x & (NN - 1)];
    xv[1] = s_sc[r0.y & (NN - 1)];
    xv[2] = s_sc[r0.z & (NN - 1)];
    xv[3] = s_sc[r0.w & (NN - 1)];
    xv[4] = s_sc[r1.x & (NN - 1)];
    xv[5] = s_sc[r1.y & (NN - 1)];
    xv[6] = s_sc[r1.z & (NN - 1)];
    xv[7] = s_sc[r1.w & (NN - 1)];

    // -------- Phase 3: block max ---------------------------------------------
    float mx = xv[0];
    #pragma unroll
    for (int j = 1; j < 8; j++) mx = fmaxf(mx, xv[j]);
    #pragma unroll
    for (int o = 16; o; o >>= 1) mx = fmaxf(mx, __shfl_xor_sync(FULL, mx, o));
    if (lane == 0) s_ws[wrp] = mx;
    __syncthreads();
    if (wrp == 0) {
        float am = (lane < 16) ? s_ws[lane] : -INFINITY;
        #pragma unroll
        for (int o = 8; o; o >>= 1) am = fmaxf(am, __shfl_xor_sync(FULL, am, o));
        if (lane == 0) s_M = am;
    }
    __syncthreads();
    const float M = s_M;

    // -------- Phase 4: exps (FMA pipe) + additive suffix-sum scan ------------
    float ev[8];
    #pragma unroll
    for (int j = 0; j < 8; j++) ev[j] = fast_exp(xv[j] - M);

    float v = 0.0f;
    #pragma unroll
    for (int j = 0; j < 8; j++) v += ev[j];

    float inc = v;                               // warp inclusive suffix sum
    #pragma unroll
    for (int d = 1; d < 32; d <<= 1) {
        const float t = __shfl_down_sync(FULL, inc, d);
        if (lane + d < 32) inc += t;
    }
    if (lane == 0) s_ws[wrp] = inc;
    __syncthreads();
    if (wrp == 0) {
        float av = (lane < 16) ? s_ws[lane] : 0.0f;
        #pragma unroll
        for (int d = 1; d < 16; d <<= 1) {
            const float t = __shfl_down_sync(FULL, av, d);
            if (lane + d < 16) av += t;
        }
        if (lane < 16) s_ws[lane] = av;          // inclusive over warps lane..15
    }
    __syncthreads();

    float ex = __shfl_down_sync(FULL, inc, 1);
    ex = (lane < 31) ? ex : 0.0f;
    const float Sc = ex + ((wrp < 15) ? s_ws[wrp + 1] : 0.0f);

    // -------- Phase 5: replay descending; batched log ------------------------
    // S_j = suffix sum at position j; sum_j log(S_j) = (sum biased_exp - 8*126)*ln2
    //                                                  + log(prod mantissa in [0.5,1))
    float rs    = Sc;
    int   ksum  = 0;
    float mprod = 1.0f;
    float xsum  = 0.0f;
    #pragma unroll
    for (int j = 7; j >= 0; j--) {
        rs += ev[j];
        const int bits = __float_as_int(rs);     // rs > 0, normal
        ksum  += (bits >> 23);                   // biased exponent (m in [0.5,1) bias 126)
        mprod *= __int_as_float((bits & 0x007FFFFF) | 0x3F000000);
        xsum  += xv[j];
    }
    const float logsum = (float)(ksum - 8 * 126) * 0.69314718f + __logf(mprod);
    float acc = (xsum - 8.0f * M) - logsum;

    // -------- Phase 6: block reduce + completion-counter finalize ------------
    #pragma unroll
    for (int o = 16; o; o >>= 1) acc += __shfl_xor_sync(FULL, acc, o);
    if (lane == 0) s_red[wrp] = acc;
    __syncthreads();
    if (tid == 0) {
        float t = 0.0f;
        #pragma unroll
        for (int w = 0; w < 16; w++) t += s_red[w];
        atomicAdd(&g_acc, (double)t);
        __threadfence();
        const unsigned int ticket = atomicAdd(&g_done, 1u);
        if (ticket == gridDim.x - 1) {
            out[0] = (float)(-g_acc / (double)gridDim.x);
            g_acc  = 0.0;
            g_done = 0u;
            __threadfence();
        }
    }
}

extern "C" void kernel_launch(void* const* d_in, const int* in_sizes, int n_in,
                              void* d_out, int out_size) {
    const float* X        = (const float*)d_in[0];
    const float* W        = (const float*)d_in[1];
    const float* bias     = (const float*)d_in[2];
    const int*   rankings = (const int*)d_in[3];
    float* out = (float*)d_out;

    const int BN = in_sizes[3];   // B * N
    const int B  = BN / NN;

    fused_kernel<<<B, T>>>(X, W, bias, rankings, out);
}